// round 1
// baseline (speedup 1.0000x reference)
#include <cuda_runtime.h>

// Problem: single-head causal attention
//   x  [1024, 256, 512] fp32
//   Wq,Wk,Wv [512, 64] fp32
//   out [1024, 256, 64] fp32
#define B_ 1024
#define T_ 256
#define C_ 512
#define H_ 64
#define M_ (B_ * T_)   // 262144 rows for the QKV projections

// Scratch for Q, K, V (device globals: allocation-free per harness rules).
__device__ float g_q[(size_t)M_ * H_];
__device__ float g_k[(size_t)M_ * H_];
__device__ float g_v[(size_t)M_ * H_];

// ---------------------------------------------------------------------------
// Kernel 1: QKV projection GEMM.  Y[M,64] = X[M,512] @ W[512,64]
// grid = (M/64, 3)  blockIdx.y selects q/k/v.  256 threads, 64x64x16 tiles,
// 4x4 micro-tile per thread.
// ---------------------------------------------------------------------------
__global__ __launch_bounds__(256, 2) void proj_kernel(
    const float* __restrict__ X,
    const float* __restrict__ Wq,
    const float* __restrict__ Wk,
    const float* __restrict__ Wv)
{
    __shared__ float As[16][64];   // As[k][m]
    __shared__ float Bs[16][64];   // Bs[k][n]

    const float* W;
    float* Y;
    if (blockIdx.y == 0)      { W = Wq; Y = g_q; }
    else if (blockIdx.y == 1) { W = Wk; Y = g_k; }
    else                      { W = Wv; Y = g_v; }

    const int tid  = threadIdx.x;
    const int row0 = blockIdx.x * 64;
    const int tx   = tid & 15;        // output col group (cols tx*4 .. +3)
    const int ty   = tid >> 4;        // output row group (rows ty*4 .. +3)

    // global-load addressing
    const int arow = tid >> 2;          // 0..63
    const int acol = (tid & 3) * 4;     // 0,4,8,12 (k within tile)
    const int brow = tid >> 4;          // 0..15    (k within tile)
    const int bcol = (tid & 15) * 4;    // 0..60

    float4 acc0 = make_float4(0.f, 0.f, 0.f, 0.f);
    float4 acc1 = make_float4(0.f, 0.f, 0.f, 0.f);
    float4 acc2 = make_float4(0.f, 0.f, 0.f, 0.f);
    float4 acc3 = make_float4(0.f, 0.f, 0.f, 0.f);

    for (int k0 = 0; k0 < C_; k0 += 16) {
        // A tile: 64 rows x 16 k   (store transposed -> As[k][m])
        float4 a4 = *reinterpret_cast<const float4*>(
            &X[(size_t)(row0 + arow) * C_ + k0 + acol]);
        As[acol + 0][arow] = a4.x;
        As[acol + 1][arow] = a4.y;
        As[acol + 2][arow] = a4.z;
        As[acol + 3][arow] = a4.w;
        // B tile: 16 k x 64 cols
        float4 b4 = *reinterpret_cast<const float4*>(
            &W[(size_t)(k0 + brow) * H_ + bcol]);
        *reinterpret_cast<float4*>(&Bs[brow][bcol]) = b4;
        __syncthreads();

        #pragma unroll
        for (int k = 0; k < 16; ++k) {
            float4 a = *reinterpret_cast<const float4*>(&As[k][ty * 4]);
            float4 b = *reinterpret_cast<const float4*>(&Bs[k][tx * 4]);
            acc0.x += a.x * b.x; acc0.y += a.x * b.y; acc0.z += a.x * b.z; acc0.w += a.x * b.w;
            acc1.x += a.y * b.x; acc1.y += a.y * b.y; acc1.z += a.y * b.z; acc1.w += a.y * b.w;
            acc2.x += a.z * b.x; acc2.y += a.z * b.y; acc2.z += a.z * b.z; acc2.w += a.z * b.w;
            acc3.x += a.w * b.x; acc3.y += a.w * b.y; acc3.z += a.w * b.z; acc3.w += a.w * b.w;
        }
        __syncthreads();
    }

    float* yp = &Y[(size_t)(row0 + ty * 4) * H_ + tx * 4];
    *reinterpret_cast<float4*>(yp + 0 * H_) = acc0;
    *reinterpret_cast<float4*>(yp + 1 * H_) = acc1;
    *reinterpret_cast<float4*>(yp + 2 * H_) = acc2;
    *reinterpret_cast<float4*>(yp + 3 * H_) = acc3;
}

// ---------------------------------------------------------------------------
// Kernel 2: causal attention, one block per batch.  K,V for the batch live in
// 128 KB dynamic smem; each thread owns one query row with online softmax.
// Warp->row-block mapping pairs (0,7)(1,6)(2,5)(3,4) on SMSPs so causal work
// is balanced across the 4 schedulers.
// ---------------------------------------------------------------------------
__global__ __launch_bounds__(256) void attn_kernel(float* __restrict__ out)
{
    extern __shared__ float sm[];
    float* Ks = sm;                 // [256][64]
    float* Vs = sm + T_ * H_;       // [256][64]

    const int b   = blockIdx.x;
    const int tid = threadIdx.x;

    // Stage K and V for this batch (fully coalesced float4 copies).
    {
        const float4* Kb = reinterpret_cast<const float4*>(g_k + (size_t)b * T_ * H_);
        const float4* Vb = reinterpret_cast<const float4*>(g_v + (size_t)b * T_ * H_);
        float4* Ks4 = reinterpret_cast<float4*>(Ks);
        float4* Vs4 = reinterpret_cast<float4*>(Vs);
        #pragma unroll
        for (int i = tid; i < T_ * H_ / 4; i += 256) {
            Ks4[i] = Kb[i];
            Vs4[i] = Vb[i];
        }
    }
    __syncthreads();

    // SMSP-balanced query-row assignment.
    const int wid  = tid >> 5;
    const int lane = tid & 31;
    const int wb   = (wid < 4) ? wid : (11 - wid);   // 0,1,2,3,7,6,5,4
    const int t    = wb * 32 + lane;

    // Load and pre-scale q (scale = 1/sqrt(64) = 0.125).
    float q[H_];
    {
        const float* qp = g_q + ((size_t)b * T_ + t) * H_;
        #pragma unroll
        for (int j = 0; j < H_; j += 4) {
            float4 v = *reinterpret_cast<const float4*>(&qp[j]);
            q[j + 0] = v.x * 0.125f;
            q[j + 1] = v.y * 0.125f;
            q[j + 2] = v.z * 0.125f;
            q[j + 3] = v.w * 0.125f;
        }
    }

    float acc[H_];
    #pragma unroll
    for (int j = 0; j < H_; ++j) acc[j] = 0.f;
    float m = -1e30f;
    float l = 0.f;

    for (int s = 0; s <= t; ++s) {
        const float4* k4 = reinterpret_cast<const float4*>(&Ks[s * H_]);
        // 4 independent partial sums to break the FFMA dependency chain.
        float w0 = 0.f, w1 = 0.f, w2 = 0.f, w3 = 0.f;
        #pragma unroll
        for (int j4 = 0; j4 < 16; ++j4) {
            float4 kk = k4[j4];
            w0 += q[4 * j4 + 0] * kk.x;
            w1 += q[4 * j4 + 1] * kk.y;
            w2 += q[4 * j4 + 2] * kk.z;
            w3 += q[4 * j4 + 3] * kk.w;
        }
        const float w = (w0 + w1) + (w2 + w3);

        const float4* v4 = reinterpret_cast<const float4*>(&Vs[s * H_]);
        if (w <= m) {
            // common path: no max update, no rescale (1 FMA per element)
            const float p = __expf(w - m);
            l += p;
            #pragma unroll
            for (int j4 = 0; j4 < 16; ++j4) {
                float4 vv = v4[j4];
                acc[4 * j4 + 0] += p * vv.x;
                acc[4 * j4 + 1] += p * vv.y;
                acc[4 * j4 + 2] += p * vv.z;
                acc[4 * j4 + 3] += p * vv.w;
            }
        } else {
            // rare path: new max (p = 1), rescale accumulators
            const float c = __expf(m - w);   // exp(-1e30 - w) -> 0 on first iter
            l = l * c + 1.f;
            #pragma unroll
            for (int j4 = 0; j4 < 16; ++j4) {
                float4 vv = v4[j4];
                acc[4 * j4 + 0] = acc[4 * j4 + 0] * c + vv.x;
                acc[4 * j4 + 1] = acc[4 * j4 + 1] * c + vv.y;
                acc[4 * j4 + 2] = acc[4 * j4 + 2] * c + vv.z;
                acc[4 * j4 + 3] = acc[4 * j4 + 3] * c + vv.w;
            }
            m = w;
        }
    }

    const float inv = 1.f / l;
    float* op = out + ((size_t)b * T_ + t) * H_;
    #pragma unroll
    for (int j = 0; j < H_; j += 4) {
        float4 o;
        o.x = acc[j + 0] * inv;
        o.y = acc[j + 1] * inv;
        o.z = acc[j + 2] * inv;
        o.w = acc[j + 3] * inv;
        *reinterpret_cast<float4*>(&op[j]) = o;
    }
}

// ---------------------------------------------------------------------------
extern "C" void kernel_launch(void* const* d_in, const int* in_sizes, int n_in,
                              void* d_out, int out_size)
{
    const float* x  = (const float*)d_in[0];
    const float* Wq = (const float*)d_in[1];
    const float* Wk = (const float*)d_in[2];
    const float* Wv = (const float*)d_in[3];
    float* out = (float*)d_out;

    // 128 KB dynamic smem opt-in for the attention kernel (idempotent,
    // capture-safe host-side attribute set).
    cudaFuncSetAttribute(attn_kernel,
                         cudaFuncAttributeMaxDynamicSharedMemorySize,
                         2 * T_ * H_ * (int)sizeof(float));

    dim3 gproj(M_ / 64, 3);
    proj_kernel<<<gproj, 256>>>(x, Wq, Wk, Wv);

    attn_kernel<<<B_, 256, 2 * T_ * H_ * (int)sizeof(float)>>>(out);
}

// round 7
// speedup vs baseline: 1.4513x; 1.4513x over previous
#include <cuda_runtime.h>
#include <cuda_bf16.h>
#include <cstdint>

// Problem: single-head causal attention
//   x [1024,256,512] fp32, Wq/Wk/Wv [512,64] fp32 -> out [1024,256,64] fp32
#define B_ 1024
#define T_ 256
#define C_ 512
#define H_ 64
#define M_ (B_ * T_)

// Scratch for Q, K, V.
__device__ float g_q[(size_t)M_ * H_];
__device__ float g_k[(size_t)M_ * H_];
__device__ float g_v[(size_t)M_ * H_];

// Pre-converted, transposed weights: [o][n=64][k=512] bf16, hi/lo split.
__device__ __align__(16) __nv_bfloat16 g_wt_hi[3 * H_ * C_];
__device__ __align__(16) __nv_bfloat16 g_wt_lo[3 * H_ * C_];

// ---------------------------------------------------------------------------
// PTX helpers (plain sm_80+ features only — NO tcgen05, build targets sm_103).
// ---------------------------------------------------------------------------
__device__ __forceinline__ uint32_t smem_u32(const void* p) {
    uint32_t a;
    asm("{ .reg .u64 t; cvta.to.shared.u64 t, %1; cvt.u32.u64 %0, t; }"
        : "=r"(a) : "l"(p));
    return a;
}
__device__ __forceinline__ void ldsm_x4(uint32_t addr, uint32_t r[4]) {
    asm volatile("ldmatrix.sync.aligned.m8n8.x4.shared.b16 {%0,%1,%2,%3}, [%4];"
                 : "=r"(r[0]), "=r"(r[1]), "=r"(r[2]), "=r"(r[3]) : "r"(addr));
}
__device__ __forceinline__ void mma_bf16(float c[4], const uint32_t a[4],
                                         uint32_t b0, uint32_t b1) {
    asm volatile(
        "mma.sync.aligned.m16n8k16.row.col.f32.bf16.bf16.f32 "
        "{%0,%1,%2,%3}, {%4,%5,%6,%7}, {%8,%9}, {%0,%1,%2,%3};"
        : "+f"(c[0]), "+f"(c[1]), "+f"(c[2]), "+f"(c[3])
        : "r"(a[0]), "r"(a[1]), "r"(a[2]), "r"(a[3]), "r"(b0), "r"(b1));
}
__device__ __forceinline__ uint32_t pack_bf16x2(float a, float b) {
    __nv_bfloat16 ha = __float2bfloat16(a);
    __nv_bfloat16 hb = __float2bfloat16(b);
    return ((uint32_t)__bfloat16_as_ushort(hb) << 16) | __bfloat16_as_ushort(ha);
}

// ---------------------------------------------------------------------------
// Kernel 0: one-time W convert+transpose+split. 3*64*512 = 98304 elems.
// grid 384 x 256 threads, k fastest -> coalesced writes.
// ---------------------------------------------------------------------------
__global__ void wconv_kernel(const float* __restrict__ Wq,
                             const float* __restrict__ Wk,
                             const float* __restrict__ Wv)
{
    const int id = blockIdx.x * 256 + threadIdx.x;   // < 98304
    const int o   = id >> 15;
    const int rem = id & 32767;
    const int n   = rem >> 9;
    const int k   = rem & 511;
    const float* W = (o == 0) ? Wq : (o == 1) ? Wk : Wv;
    const float v = W[(size_t)k * H_ + n];
    const __nv_bfloat16 h = __float2bfloat16(v);
    g_wt_hi[id] = h;
    g_wt_lo[id] = __float2bfloat16(v - __bfloat162float(h));
}

// ---------------------------------------------------------------------------
// Kernel 1: QKV projection on HMMA (mma.sync bf16, 3-pass hi/lo split).
// CTA = 128 token rows x {Q,K,V}. 12 warps: warp w -> output (w>>2),
// rows (w&3)*32. K chunked at 64; smem rows padded to 144B for conflict-free
// ldmatrix.
// ---------------------------------------------------------------------------
#define ROWB   144            // padded row stride in bytes (64 bf16 + 8 pad)
#define SM_A_HI 0             // [128][ROWB]  = 18432 B
#define SM_A_LO 18432
#define SM_B    36864         // 6 tiles of [64][ROWB] = 9216 B each
#define PROJ_SMEM (36864 + 6 * 9216)   // 92160 B

__global__ __launch_bounds__(384, 1)
void proj_kernel(const float* __restrict__ X)
{
    extern __shared__ __align__(16) char smem[];
    const uint32_t sb = smem_u32(smem);
    const int tid  = threadIdx.x;
    const int lane = tid & 31;
    const int wid  = tid >> 5;
    const int row0 = blockIdx.x * 128;

    const int o  = wid >> 2;          // 0..2 : q/k/v
    const int m0 = (wid & 3) * 32;    // warp's row base within tile

    float acc[2][8][4];
    #pragma unroll
    for (int mt = 0; mt < 2; ++mt)
        #pragma unroll
        for (int nt = 0; nt < 8; ++nt)
            #pragma unroll
            for (int i = 0; i < 4; ++i) acc[mt][nt][i] = 0.f;

    // ldmatrix lane -> row/koff mapping (x4: lanes 0-7 mat0, 8-15 mat1, ...)
    const int lr = lane & 7;
    const int ls = lane >> 3;
    const uint32_t kpart = (uint32_t)((ls >> 1) << 3) * 2;   // bytes (k +8 for mats 2,3)
    uint32_t a_off[2], b_off[4];
    #pragma unroll
    for (int mt = 0; mt < 2; ++mt)
        a_off[mt] = (uint32_t)(m0 + mt * 16 + lr + ((ls & 1) << 3)) * ROWB + kpart;
    #pragma unroll
    for (int np = 0; np < 4; ++np)
        b_off[np] = (uint32_t)(np * 16 + lr + ((ls & 1) << 3)) * ROWB + kpart;

    const uint32_t aHi = sb + SM_A_HI;
    const uint32_t aLo = sb + SM_A_LO;
    const uint32_t bHi = sb + SM_B + (uint32_t)(o * 2 + 0) * 9216;
    const uint32_t bLo = sb + SM_B + (uint32_t)(o * 2 + 1) * 9216;

    for (int ch = 0; ch < 8; ++ch) {
        const int k0 = ch * 64;
        if (ch) __syncthreads();      // prev readers done before overwrite

        // ---- X chunk [128 x 64] fp32 -> bf16 hi/lo in padded smem ----
        for (int id = tid; id < 2048; id += 384) {
            const int r  = id >> 4;
            const int c4 = (id & 15) * 4;
            const float4 v = *reinterpret_cast<const float4*>(
                &X[(size_t)(row0 + r) * C_ + k0 + c4]);
            const uint32_t d = (uint32_t)r * ROWB + (uint32_t)c4 * 2;
            const __nv_bfloat16 h0 = __float2bfloat16(v.x);
            const __nv_bfloat16 h1 = __float2bfloat16(v.y);
            const __nv_bfloat16 h2 = __float2bfloat16(v.z);
            const __nv_bfloat16 h3 = __float2bfloat16(v.w);
            *reinterpret_cast<uint32_t*>(smem + SM_A_HI + d) =
                ((uint32_t)__bfloat16_as_ushort(h1) << 16) | __bfloat16_as_ushort(h0);
            *reinterpret_cast<uint32_t*>(smem + SM_A_HI + d + 4) =
                ((uint32_t)__bfloat16_as_ushort(h3) << 16) | __bfloat16_as_ushort(h2);
            *reinterpret_cast<uint32_t*>(smem + SM_A_LO + d) =
                pack_bf16x2(v.x - __bfloat162float(h0), v.y - __bfloat162float(h1));
            *reinterpret_cast<uint32_t*>(smem + SM_A_LO + d + 4) =
                pack_bf16x2(v.z - __bfloat162float(h2), v.w - __bfloat162float(h3));
        }

        // ---- Stage B tiles: copy pre-split bf16 W chunk (16B moves) ----
        #pragma unroll
        for (int it = 0; it < 8; ++it) {
            const int id  = tid + it * 384;          // < 3072
            const int o2  = id >> 9;                 // 0..5  (o*2+h)
            const int rem = id & 511;
            const int r   = rem >> 3;
            const int j   = rem & 7;
            const __nv_bfloat16* src = (o2 & 1) ? g_wt_lo : g_wt_hi;
            const float4 v = *reinterpret_cast<const float4*>(
                &src[(size_t)(o2 >> 1) * 32768 + (size_t)r * 512 + k0 + j * 8]);
            *reinterpret_cast<float4*>(
                smem + SM_B + (size_t)o2 * 9216 + (size_t)r * ROWB + j * 16) = v;
        }
        __syncthreads();

        // ---- 4 k16 steps, 3 passes each ----
        #pragma unroll
        for (int s = 0; s < 4; ++s) {
            const uint32_t kb = (uint32_t)s * 32;    // 16 bf16 = 32 B
            uint32_t ah[2][4], al[2][4], bh[4][4], bl[4][4];
            ldsm_x4(aHi + a_off[0] + kb, ah[0]);
            ldsm_x4(aHi + a_off[1] + kb, ah[1]);
            ldsm_x4(aLo + a_off[0] + kb, al[0]);
            ldsm_x4(aLo + a_off[1] + kb, al[1]);
            #pragma unroll
            for (int np = 0; np < 4; ++np) {
                ldsm_x4(bHi + b_off[np] + kb, bh[np]);
                ldsm_x4(bLo + b_off[np] + kb, bl[np]);
            }
            // pass 1: hi*hi
            #pragma unroll
            for (int mt = 0; mt < 2; ++mt)
                #pragma unroll
                for (int nt = 0; nt < 8; ++nt)
                    mma_bf16(acc[mt][nt], ah[mt],
                             bh[nt >> 1][nt & 1], bh[nt >> 1][2 + (nt & 1)]);
            // pass 2: hi*lo
            #pragma unroll
            for (int mt = 0; mt < 2; ++mt)
                #pragma unroll
                for (int nt = 0; nt < 8; ++nt)
                    mma_bf16(acc[mt][nt], ah[mt],
                             bl[nt >> 1][nt & 1], bl[nt >> 1][2 + (nt & 1)]);
            // pass 3: lo*hi
            #pragma unroll
            for (int mt = 0; mt < 2; ++mt)
                #pragma unroll
                for (int nt = 0; nt < 8; ++nt)
                    mma_bf16(acc[mt][nt], al[mt],
                             bh[nt >> 1][nt & 1], bh[nt >> 1][2 + (nt & 1)]);
        }
    }

    // ---- Epilogue: fp32 accumulators -> g_q/g_k/g_v ----
    const int g  = lane >> 2;
    const int tg = lane & 3;
    float* dst = (o == 0) ? g_q : (o == 1) ? g_k : g_v;
    #pragma unroll
    for (int mt = 0; mt < 2; ++mt) {
        #pragma unroll
        for (int nt = 0; nt < 8; ++nt) {
            const int row = row0 + m0 + mt * 16 + g;
            const int col = nt * 8 + tg * 2;
            float2 lo2 = make_float2(acc[mt][nt][0], acc[mt][nt][1]);
            float2 hi2 = make_float2(acc[mt][nt][2], acc[mt][nt][3]);
            *reinterpret_cast<float2*>(&dst[(size_t)row * H_ + col])       = lo2;
            *reinterpret_cast<float2*>(&dst[(size_t)(row + 8) * H_ + col]) = hi2;
        }
    }
}

// ---------------------------------------------------------------------------
// Kernel 2: causal attention (unchanged): one block per batch, K,V in 128 KB
// smem, per-thread query row, online softmax, SMSP-balanced warp mapping.
// ---------------------------------------------------------------------------
__global__ __launch_bounds__(256) void attn_kernel(float* __restrict__ out)
{
    extern __shared__ float sm[];
    float* Ks = sm;
    float* Vs = sm + T_ * H_;

    const int b   = blockIdx.x;
    const int tid = threadIdx.x;

    {
        const float4* Kb = reinterpret_cast<const float4*>(g_k + (size_t)b * T_ * H_);
        const float4* Vb = reinterpret_cast<const float4*>(g_v + (size_t)b * T_ * H_);
        float4* Ks4 = reinterpret_cast<float4*>(Ks);
        float4* Vs4 = reinterpret_cast<float4*>(Vs);
        #pragma unroll
        for (int i = tid; i < T_ * H_ / 4; i += 256) {
            Ks4[i] = Kb[i];
            Vs4[i] = Vb[i];
        }
    }
    __syncthreads();

    const int wid  = tid >> 5;
    const int lane = tid & 31;
    const int wb   = (wid < 4) ? wid : (11 - wid);
    const int t    = wb * 32 + lane;

    float q[H_];
    {
        const float* qp = g_q + ((size_t)b * T_ + t) * H_;
        #pragma unroll
        for (int j = 0; j < H_; j += 4) {
            float4 v = *reinterpret_cast<const float4*>(&qp[j]);
            q[j + 0] = v.x * 0.125f;
            q[j + 1] = v.y * 0.125f;
            q[j + 2] = v.z * 0.125f;
            q[j + 3] = v.w * 0.125f;
        }
    }

    float acc[H_];
    #pragma unroll
    for (int j = 0; j < H_; ++j) acc[j] = 0.f;
    float m = -1e30f;
    float l = 0.f;

    for (int s = 0; s <= t; ++s) {
        const float4* k4 = reinterpret_cast<const float4*>(&Ks[s * H_]);
        float w0 = 0.f, w1 = 0.f, w2 = 0.f, w3 = 0.f;
        #pragma unroll
        for (int j4 = 0; j4 < 16; ++j4) {
            float4 kk = k4[j4];
            w0 += q[4 * j4 + 0] * kk.x;
            w1 += q[4 * j4 + 1] * kk.y;
            w2 += q[4 * j4 + 2] * kk.z;
            w3 += q[4 * j4 + 3] * kk.w;
        }
        const float w = (w0 + w1) + (w2 + w3);

        const float4* v4 = reinterpret_cast<const float4*>(&Vs[s * H_]);
        if (w <= m) {
            const float p = __expf(w - m);
            l += p;
            #pragma unroll
            for (int j4 = 0; j4 < 16; ++j4) {
                float4 vv = v4[j4];
                acc[4 * j4 + 0] += p * vv.x;
                acc[4 * j4 + 1] += p * vv.y;
                acc[4 * j4 + 2] += p * vv.z;
                acc[4 * j4 + 3] += p * vv.w;
            }
        } else {
            const float c = __expf(m - w);
            l = l * c + 1.f;
            #pragma unroll
            for (int j4 = 0; j4 < 16; ++j4) {
                float4 vv = v4[j4];
                acc[4 * j4 + 0] = acc[4 * j4 + 0] * c + vv.x;
                acc[4 * j4 + 1] = acc[4 * j4 + 1] * c + vv.y;
                acc[4 * j4 + 2] = acc[4 * j4 + 2] * c + vv.z;
                acc[4 * j4 + 3] = acc[4 * j4 + 3] * c + vv.w;
            }
            m = w;
        }
    }

    const float inv = 1.f / l;
    float* op = out + ((size_t)b * T_ + t) * H_;
    #pragma unroll
    for (int j = 0; j < H_; j += 4) {
        float4 o;
        o.x = acc[j + 0] * inv;
        o.y = acc[j + 1] * inv;
        o.z = acc[j + 2] * inv;
        o.w = acc[j + 3] * inv;
        *reinterpret_cast<float4*>(&op[j]) = o;
    }
}

// ---------------------------------------------------------------------------
extern "C" void kernel_launch(void* const* d_in, const int* in_sizes, int n_in,
                              void* d_out, int out_size)
{
    const float* x  = (const float*)d_in[0];
    const float* Wq = (const float*)d_in[1];
    const float* Wk = (const float*)d_in[2];
    const float* Wv = (const float*)d_in[3];
    float* out = (float*)d_out;

    cudaFuncSetAttribute(proj_kernel,
                         cudaFuncAttributeMaxDynamicSharedMemorySize, PROJ_SMEM);
    cudaFuncSetAttribute(attn_kernel,
                         cudaFuncAttributeMaxDynamicSharedMemorySize,
                         2 * T_ * H_ * (int)sizeof(float));

    wconv_kernel<<<384, 256>>>(Wq, Wk, Wv);
    proj_kernel<<<M_ / 128, 384, PROJ_SMEM>>>(x);
    attn_kernel<<<B_, 256, 2 * T_ * H_ * (int)sizeof(float)>>>(out);
}